// round 5
// baseline (speedup 1.0000x reference)
#include <cuda_runtime.h>
#include <cstdint>
#include <cstddef>

#define TST 192
#define BAT 256
#define HID 512
#define G4  2048
#define RWS (TST*BAT)

__device__ float g_X[(size_t)RWS*64];
__device__ float g_XZ[(size_t)RWS*G4];
__device__ float g_H1[(size_t)RWS*HID];
__device__ float g_H2[(size_t)RWS*HID];
__device__ float g_Hb[2][64*BAT*8];      // fragment-packed h ping-pong [kb][b][8]
__device__ float g_Wk1p[64*G4];
__device__ float g_Wk2r[HID*G4];
__device__ unsigned g_cnt[128];
__device__ volatile unsigned g_flag[128];

__device__ __forceinline__ float rna(float x){
    unsigned r; asm("cvt.rna.tf32.f32 %0, %1;" : "=r"(r) : "f"(x));
    return __uint_as_float(r);
}
__device__ __forceinline__ void mma8(float* d, float a0,float a1,float a2,float a3,
                                     float b0,float b1){
    asm volatile("mma.sync.aligned.m16n8k8.row.col.f32.tf32.tf32.f32 "
        "{%0,%1,%2,%3}, {%4,%5,%6,%7}, {%8,%9}, {%0,%1,%2,%3};\n"
        : "+f"(d[0]),"+f"(d[1]),"+f"(d[2]),"+f"(d[3])
        : "r"(__float_as_uint(a0)),"r"(__float_as_uint(a1)),
          "r"(__float_as_uint(a2)),"r"(__float_as_uint(a3)),
          "r"(__float_as_uint(b0)),"r"(__float_as_uint(b1)));
}
__device__ __forceinline__ unsigned su32(const void* p){
    return (unsigned)__cvta_generic_to_shared(p);
}
__device__ __forceinline__ void cp16(unsigned dst, const void* src){
    asm volatile("cp.async.cg.shared.global [%0], [%1], 16;" :: "r"(dst), "l"(src));
}
__device__ __forceinline__ void cpc(){ asm volatile("cp.async.commit_group;"); }
template<int N> __device__ __forceinline__ void cpw(){
    asm volatile("cp.async.wait_group %0;" :: "n"(N));
}
__device__ __forceinline__ void barwg(int id){
    asm volatile("bar.sync %0, 128;" :: "r"(id) : "memory");
}
__device__ __forceinline__ float sigf(float x){ return 1.f/(1.f+__expf(-x)); }
__device__ __forceinline__ float tanhf_(float x){
    float e=__expf(-2.f*fabsf(x)); return copysignf((1.f-e)/(1.f+e), x);
}

// ---------------- prep ----------------
__global__ void prep_k(const float* __restrict__ xc, const int* __restrict__ c0,
                       const int* __restrict__ c1, const float* __restrict__ e0,
                       const float* __restrict__ e1, const float* __restrict__ Wk1,
                       const float* __restrict__ Wk2){
    const size_t N1=(size_t)RWS*64, N2=N1+64*G4, NT=N2+(size_t)HID*G4;
    for(size_t i=(size_t)blockIdx.x*blockDim.x+threadIdx.x; i<NT;
        i+=(size_t)gridDim.x*blockDim.x){
        if(i<N1){
            int r=(int)(i>>6), cc=(int)(i&63), t=r>>8, b=r&255;
            float v=0.f;
            if(cc<8)       v=xc[(b*TST+t)*8+cc];
            else if(cc<40) v=e0[(size_t)c0[b*TST+t]*32+(cc-8)];
            else if(cc<56) v=e1[(size_t)c1[b*TST+t]*16+(cc-40)];
            g_X[i]=rna(v);
        } else if(i<N2){
            size_t j=i-N1; int k=(int)(j>>11);
            g_Wk1p[j]=(k<56)? rna(Wk1[(size_t)k*G4+(j&2047)]) : 0.f;
        } else {
            size_t j=i-N2; g_Wk2r[j]=rna(Wk2[j]);
        }
    }
}

__global__ void zero_k(){
    int i=blockIdx.x*blockDim.x+threadIdx.x;
    if(i<2*64*BAT*8) ((float*)g_Hb)[i]=0.f;
}

// ---------------- GEMM: C[M,2048] = A[M,K]@W[K,2048] + bias ----------------
__global__ __launch_bounds__(128) void gemm64(const float* __restrict__ A,
        const float* __restrict__ W, const float* __restrict__ bias,
        float* __restrict__ C, int K){
    extern __shared__ float sm[];
    const int tid=threadIdx.x, l=tid&31, w=tid>>5, wm=w>>1, wn=w&1;
    const int g=l>>2, tg=l&3;
    const int row0=blockIdx.y*64, col0=blockIdx.x*64;
    float acc[2][4][4];
#pragma unroll
    for(int m=0;m<2;m++) for(int n=0;n<4;n++) for(int q=0;q<4;q++) acc[m][n][q]=0.f;
    const int NC=K>>6;

    auto issue=[&](int c){
        float* As_=sm+(c&1)*9216; float* Bs_=As_+4608;
#pragma unroll
        for(int q=0;q<8;q++){ int e=tid+128*q, r=e>>4, s=e&15;
            cp16(su32(As_+r*72+s*4), A+(size_t)(row0+r)*K + c*64 + s*4); }
#pragma unroll
        for(int q=0;q<8;q++){ int e=tid+128*q, r=e>>4, s=e&15;
            cp16(su32(Bs_+r*72+s*4), W+(size_t)(c*64+r)*G4 + col0 + s*4); }
    };
    issue(0); cpc();
    for(int c=0;c<NC;c++){
        if(c+1<NC){ issue(c+1); cpc(); cpw<1>(); } else cpw<0>();
        __syncthreads();
        const float* As_=sm+(c&1)*9216; const float* Bs_=As_+4608;
#pragma unroll
        for(int kb=0;kb<8;kb++){
            float a[2][4];
#pragma unroll
            for(int mt=0;mt<2;mt++){
                int r=wm*32+mt*16+g;
                a[mt][0]=As_[r*72+kb*8+tg];     a[mt][1]=As_[(r+8)*72+kb*8+tg];
                a[mt][2]=As_[r*72+kb*8+tg+4];   a[mt][3]=As_[(r+8)*72+kb*8+tg+4];
            }
#pragma unroll
            for(int nt=0;nt<4;nt++){
                int cc=wn*32+nt*8+g;
                float b0=Bs_[(kb*8+tg)*72+cc], b1=Bs_[(kb*8+tg+4)*72+cc];
                mma8(acc[0][nt],a[0][0],a[0][1],a[0][2],a[0][3],b0,b1);
                mma8(acc[1][nt],a[1][0],a[1][1],a[1][2],a[1][3],b0,b1);
            }
        }
        __syncthreads();
    }
#pragma unroll
    for(int nt=0;nt<4;nt++){
        int cc=col0+wn*32+nt*8+tg*2;
        float bx=bias[cc], by=bias[cc+1];
#pragma unroll
        for(int mt=0;mt<2;mt++){
            int r=row0+wm*32+mt*16+g;
            float2 v0={acc[mt][nt][0]+bx, acc[mt][nt][1]+by};
            float2 v1={acc[mt][nt][2]+bx, acc[mt][nt][3]+by};
            *(float2*)&C[(size_t)r*G4+cc]=v0;
            *(float2*)&C[(size_t)(r+8)*G4+cc]=v1;
        }
    }
}

// ---------------- persistent LSTM layer ----------------
// 128 CTAs = 4 bg x 32 strips; 512 threads = 4 warp-groups, 4-way K-split.
// wg g: k in [g*128, g*128+128) = kb in [g*16, g*16+16). 8 chunks of 2 kbl.
// 4-stage cp.async per wg, wg-scoped named barrier, issue-ahead-2.
// Reduction buffers reuse each wg's As region (wg 1..3) after last chunk.
__global__ __launch_bounds__(512) void lstm_k(const float* __restrict__ xz,
        float* __restrict__ hout, const float* __restrict__ Wr){
    extern __shared__ float sm[];
    float2* Wpk=(float2*)sm;            // 16384 float2 = 128 KB
    const int tid=threadIdx.x, l=tid&31, w=tid>>5;
    const int wg=w>>2, wl=w&3;
    const int wm=wl>>1, wn=wl&1;
    const int g=l>>2, tg=l&3;
    const int wtid=tid&127;
    const int strip=blockIdx.x&31, bg=blockIdx.x>>5;
    float* As0=sm+32768+wg*4096;        // 4 stages x 1024 floats per wg

    // prepack Wr slice into B-fragment lane order
    for(int e=tid;e<16384;e+=512){
        int tg_=e&3, ci=(e>>2)&63, kb=e>>8;
        int nt=ci>>4, wn_=(ci>>3)&1, gg=ci&7;
        int gcol=nt*HID + strip*16 + wn_*8 + gg;
        int k0=kb*8+tg_;
        float2 v; v.x=rna(Wr[(size_t)k0*G4+gcol]); v.y=rna(Wr[(size_t)(k0+4)*G4+gcol]);
        Wpk[e]=v;
    }
    __syncthreads();

    float cst[2][4];
#pragma unroll
    for(int m=0;m<2;m++) for(int q=0;q<4;q++) cst[m][q]=0.f;
    float xzp[2][4][4];
    unsigned sense=0;
    const int barid=wg+1;

    // xz prefetch (wg1 only)
    auto pfxz=[&](int tt){
        const float* xr=xz+(size_t)tt*BAT*G4;
#pragma unroll
        for(int mt=0;mt<2;mt++)
#pragma unroll
            for(int nt=0;nt<4;nt++){
                int b=bg*64+wm*32+mt*16+g;
                int cc=nt*HID+strip*16+wn*8+tg*2;
                float2 v0=*(const float2*)&xr[(size_t)b*G4+cc];
                float2 v1=*(const float2*)&xr[(size_t)(b+8)*G4+cc];
                xzp[mt][nt][0]=v0.x; xzp[mt][nt][1]=v0.y;
                xzp[mt][nt][2]=v1.x; xzp[mt][nt][3]=v1.y;
            }
    };
    if(wg==1) pfxz(0);

    for(int t=0;t<TST;t++){
        const float* hb=g_Hb[t&1];
        float* hn=g_Hb[(t&1)^1];

        auto issueA=[&](int c){
            float* dst=As0+(c&3)*1024;
            const int kb0=wg*16+c*2;
#pragma unroll
            for(int q=0;q<2;q++){
                int e=wtid+128*q;
                int kbl=q, rem=e&127, r=rem>>1, hf=rem&1;
                cp16(su32(dst+(kbl*64+r)*8+hf*4),
                     hb + ((size_t)(kb0+kbl)*BAT + bg*64 + r)*8 + hf*4);
            }
        };
        issueA(0); cpc();
        issueA(1); cpc();

        float acc[2][4][4];
        if(wg==1){
#pragma unroll
            for(int mt=0;mt<2;mt++) for(int nt=0;nt<4;nt++) for(int q=0;q<4;q++)
                acc[mt][nt][q]=xzp[mt][nt][q];
            if(t+1<TST) pfxz(t+1);
        } else {
#pragma unroll
            for(int m=0;m<2;m++) for(int n=0;n<4;n++) for(int q=0;q<4;q++)
                acc[m][n][q]=0.f;
        }

        for(int c=0;c<8;c++){
            if(c<6){ issueA(c+2); cpc(); cpw<2>(); }
            else if(c==6){ cpw<1>(); }
            else { cpw<0>(); }
            barwg(barid);
            const float* A_=As0+(c&3)*1024;
#pragma unroll
            for(int kbl=0;kbl<2;kbl++){
                const int kbg=wg*16+c*2+kbl;
                float2 v0[2], v1[2];
#pragma unroll
                for(int mt=0;mt<2;mt++){
                    int r=wm*32+mt*16+g;
                    v0[mt]=*(const float2*)&A_[(kbl*64+r)*8+tg*2];
                    v1[mt]=*(const float2*)&A_[(kbl*64+r+8)*8+tg*2];
                }
#pragma unroll
                for(int nt=0;nt<4;nt++){
                    float2 bv=Wpk[(kbg*64 + nt*16+wn*8+g)*4 + tg];
                    mma8(acc[0][nt], v0[0].x,v1[0].x,v0[0].y,v1[0].y, bv.x,bv.y);
                    mma8(acc[1][nt], v0[1].x,v1[1].x,v0[1].y,v1[1].y, bv.x,bv.y);
                }
            }
            barwg(barid);
        }

        // K-split reduction: wg1..3 dump acc (float4, rotated swizzle) into own As region
        if(wg!=0){
            float4* redw=(float4*)(sm+32768+wg*4096);
#pragma unroll
            for(int mt=0;mt<2;mt++)
#pragma unroll
                for(int nt=0;nt<4;nt++){
                    int jj=mt*4+nt;
                    float4 v={acc[mt][nt][0],acc[mt][nt][1],acc[mt][nt][2],acc[mt][nt][3]};
                    redw[wtid*8 + ((jj+wtid)&7)]=v;
                }
        }
        __syncthreads();
        if(wg==0){
#pragma unroll
            for(int mt=0;mt<2;mt++){
                float hq[4][2]; // [q pair][..] -> store later
#pragma unroll
                for(int nt=0;nt<4;nt++){
                    int jj=mt*4+nt;
#pragma unroll
                    for(int ww=1;ww<4;ww++){
                        const float4* redw=(const float4*)(sm+32768+ww*4096);
                        float4 v=redw[wtid*8 + ((jj+wtid)&7)];
                        acc[mt][nt][0]+=v.x; acc[mt][nt][1]+=v.y;
                        acc[mt][nt][2]+=v.z; acc[mt][nt][3]+=v.w;
                    }
                }
#pragma unroll
                for(int q=0;q<4;q++){
                    float ig=sigf(acc[mt][0][q]);
                    float fg=sigf(acc[mt][1][q]);
                    float gv=tanhf_(acc[mt][2][q]);
                    float og=sigf(acc[mt][3][q]);
                    float cc_=fg*cst[mt][q]+ig*gv;
                    cst[mt][q]=cc_;
                    hq[q>>1][q&1]=rna(og*tanhf_(cc_));
                }
                // stores: hout pairs contiguous in U -> STG.64
#pragma unroll
                for(int p=0;p<2;p++){
                    int b=bg*64+wm*32+mt*16+p*8+g;
                    int U0=strip*16+wn*8+tg*2;
                    float2 hv={hq[p][0],hq[p][1]};
                    *(float2*)&hout[(size_t)(t*BAT+b)*HID+U0]=hv;
#pragma unroll
                    for(int s=0;s<2;s++){
                        int U=U0+s;
                        int kb=U>>3, kp=U&7, j=(kp&3)*2+(kp>>2);
                        hn[((size_t)kb*BAT+b)*8+j]=hq[p][s];
                    }
                }
            }
        }

        // per-bg grid barrier (32 CTAs; even flips -> replay-safe)
        __threadfence(); __syncthreads();
        if(tid==0){
            unsigned tgt=sense^1u;
            if(atomicAdd(&g_cnt[bg*32],1u)==31u){
                g_cnt[bg*32]=0u; __threadfence(); g_flag[bg*32]=tgt;
            } else { while(g_flag[bg*32]!=tgt){} __threadfence(); }
        }
        __syncthreads();
        sense^=1u;
    }
}

// ---------------- heads ----------------
__global__ __launch_bounds__(256) void head_k(const float* __restrict__ h,
        const float* __restrict__ Wmu, const float* __restrict__ bmu,
        const float* __restrict__ Wsig, const float* __restrict__ bsig,
        float* __restrict__ out){
    int w=threadIdx.x>>5, l=threadIdx.x&31;
    int r=blockIdx.x*8+w;
    const float* hr=h+(size_t)r*HID;
    float smu=0.f, ssg=0.f;
    for(int k=l;k<HID;k+=32){ float hv=hr[k]; smu+=hv*Wmu[k]; ssg+=hv*Wsig[k]; }
#pragma unroll
    for(int o=16;o;o>>=1){
        smu+=__shfl_xor_sync(0xFFFFFFFFu,smu,o);
        ssg+=__shfl_xor_sync(0xFFFFFFFFu,ssg,o);
    }
    if(l==0){
        int t=r>>8, b=r&255;
        out[b*TST+t]=smu+bmu[0];
        float x=ssg+bsig[0];
        out[RWS + b*TST+t]=(x>20.f)? x : log1pf(__expf(x));
    }
}

extern "C" void kernel_launch(void* const* d_in, const int* in_sizes, int n_in,
                              void* d_out, int out_size){
    const float* xc  =(const float*)d_in[0];
    const int*   c0  =(const int*  )d_in[1];
    const int*   c1  =(const int*  )d_in[2];
    const float* e0  =(const float*)d_in[3];
    const float* e1  =(const float*)d_in[4];
    const float* Wk1 =(const float*)d_in[5];
    const float* Wr1 =(const float*)d_in[6];
    const float* b1  =(const float*)d_in[7];
    const float* Wk2 =(const float*)d_in[8];
    const float* Wr2 =(const float*)d_in[9];
    const float* b2  =(const float*)d_in[10];
    const float* Wmu =(const float*)d_in[11];
    const float* bmu =(const float*)d_in[12];
    const float* Wsig=(const float*)d_in[13];
    const float* bsig=(const float*)d_in[14];
    float* out=(float*)d_out;

    cudaFuncSetAttribute(lstm_k, cudaFuncAttributeMaxDynamicSharedMemorySize, 196608);
    cudaFuncSetAttribute(gemm64, cudaFuncAttributeMaxDynamicSharedMemorySize, 73728);

    void *pX,*pXZ,*pH1,*pH2,*pW1,*pW2;
    cudaGetSymbolAddress(&pX,  g_X);
    cudaGetSymbolAddress(&pXZ, g_XZ);
    cudaGetSymbolAddress(&pH1, g_H1);
    cudaGetSymbolAddress(&pH2, g_H2);
    cudaGetSymbolAddress(&pW1, g_Wk1p);
    cudaGetSymbolAddress(&pW2, g_Wk2r);

    prep_k<<<4096,256>>>(xc,c0,c1,e0,e1,Wk1,Wk2);
    zero_k<<<1024,256>>>();
    gemm64<<<dim3(32,RWS/64),128,73728>>>((const float*)pX,(const float*)pW1,b1,(float*)pXZ,64);
    lstm_k<<<128,512,196608>>>((const float*)pXZ,(float*)pH1,Wr1);
    zero_k<<<1024,256>>>();
    gemm64<<<dim3(32,RWS/64),128,73728>>>((const float*)pH1,(const float*)pW2,b2,(float*)pXZ,512);
    lstm_k<<<128,512,196608>>>((const float*)pXZ,(float*)pH2,Wr2);
    head_k<<<RWS/8,256>>>((const float*)pH2,Wmu,bmu,Wsig,bsig,out);
}

// round 6
// speedup vs baseline: 1.0627x; 1.0627x over previous
#include <cuda_runtime.h>
#include <cstdint>
#include <cstddef>

#define TST 192
#define BAT 256
#define HID 512
#define G4  2048
#define RWS (TST*BAT)

__device__ float g_X[(size_t)RWS*64];
__device__ float g_XZ[(size_t)RWS*G4];
__device__ float g_H1[(size_t)RWS*HID];
__device__ float g_H2[(size_t)RWS*HID];
__device__ float g_Hb[2][64*BAT*8];      // fragment-packed h ping-pong [kb][b][8]
__device__ float g_Wk1p[64*G4];
__device__ float g_Wk2r[HID*G4];
__device__ volatile unsigned g_sync[4096];   // 128 flags, one per 128B line

__device__ __forceinline__ float rna(float x){
    unsigned r; asm("cvt.rna.tf32.f32 %0, %1;" : "=r"(r) : "f"(x));
    return __uint_as_float(r);
}
__device__ __forceinline__ void mma8(float* d, float a0,float a1,float a2,float a3,
                                     float b0,float b1){
    asm volatile("mma.sync.aligned.m16n8k8.row.col.f32.tf32.tf32.f32 "
        "{%0,%1,%2,%3}, {%4,%5,%6,%7}, {%8,%9}, {%0,%1,%2,%3};\n"
        : "+f"(d[0]),"+f"(d[1]),"+f"(d[2]),"+f"(d[3])
        : "r"(__float_as_uint(a0)),"r"(__float_as_uint(a1)),
          "r"(__float_as_uint(a2)),"r"(__float_as_uint(a3)),
          "r"(__float_as_uint(b0)),"r"(__float_as_uint(b1)));
}
__device__ __forceinline__ unsigned su32(const void* p){
    return (unsigned)__cvta_generic_to_shared(p);
}
__device__ __forceinline__ void cp16(unsigned dst, const void* src){
    asm volatile("cp.async.cg.shared.global [%0], [%1], 16;" :: "r"(dst), "l"(src));
}
__device__ __forceinline__ void cpc(){ asm volatile("cp.async.commit_group;"); }
template<int N> __device__ __forceinline__ void cpw(){
    asm volatile("cp.async.wait_group %0;" :: "n"(N));
}
__device__ __forceinline__ void barwg(int id){
    asm volatile("bar.sync %0, 128;" :: "r"(id) : "memory");
}
__device__ __forceinline__ float sigf(float x){ return 1.f/(1.f+__expf(-x)); }
__device__ __forceinline__ float tanhf_(float x){
    float e=__expf(-2.f*fabsf(x)); return copysignf((1.f-e)/(1.f+e), x);
}

// ---------------- prep ----------------
__global__ void prep_k(const float* __restrict__ xc, const int* __restrict__ c0,
                       const int* __restrict__ c1, const float* __restrict__ e0,
                       const float* __restrict__ e1, const float* __restrict__ Wk1,
                       const float* __restrict__ Wk2){
    const size_t N1=(size_t)RWS*64, N2=N1+64*G4, NT=N2+(size_t)HID*G4;
    for(size_t i=(size_t)blockIdx.x*blockDim.x+threadIdx.x; i<NT;
        i+=(size_t)gridDim.x*blockDim.x){
        if(i<N1){
            int r=(int)(i>>6), cc=(int)(i&63), t=r>>8, b=r&255;
            float v=0.f;
            if(cc<8)       v=xc[(b*TST+t)*8+cc];
            else if(cc<40) v=e0[(size_t)c0[b*TST+t]*32+(cc-8)];
            else if(cc<56) v=e1[(size_t)c1[b*TST+t]*16+(cc-40)];
            g_X[i]=rna(v);
        } else if(i<N2){
            size_t j=i-N1; int k=(int)(j>>11);
            g_Wk1p[j]=(k<56)? rna(Wk1[(size_t)k*G4+(j&2047)]) : 0.f;
        } else {
            size_t j=i-N2; g_Wk2r[j]=rna(Wk2[j]);
        }
    }
}

__global__ void zero_k(){
    int i=blockIdx.x*blockDim.x+threadIdx.x;
    if(i<2*64*BAT*8) ((float*)g_Hb)[i]=0.f;
}

__global__ void rst_k(){
    if(threadIdx.x<128) g_sync[threadIdx.x*32]=0u;
}

// ---------------- GEMM: C[M,2048] = A[M,K]@W[K,2048] + bias ----------------
__global__ __launch_bounds__(128) void gemm64(const float* __restrict__ A,
        const float* __restrict__ W, const float* __restrict__ bias,
        float* __restrict__ C, int K){
    extern __shared__ float sm[];
    const int tid=threadIdx.x, l=tid&31, w=tid>>5, wm=w>>1, wn=w&1;
    const int g=l>>2, tg=l&3;
    const int row0=blockIdx.y*64, col0=blockIdx.x*64;
    float acc[2][4][4];
#pragma unroll
    for(int m=0;m<2;m++) for(int n=0;n<4;n++) for(int q=0;q<4;q++) acc[m][n][q]=0.f;
    const int NC=K>>6;

    auto issue=[&](int c){
        float* As_=sm+(c&1)*9216; float* Bs_=As_+4608;
#pragma unroll
        for(int q=0;q<8;q++){ int e=tid+128*q, r=e>>4, s=e&15;
            cp16(su32(As_+r*72+s*4), A+(size_t)(row0+r)*K + c*64 + s*4); }
#pragma unroll
        for(int q=0;q<8;q++){ int e=tid+128*q, r=e>>4, s=e&15;
            cp16(su32(Bs_+r*72+s*4), W+(size_t)(c*64+r)*G4 + col0 + s*4); }
    };
    issue(0); cpc();
    for(int c=0;c<NC;c++){
        if(c+1<NC){ issue(c+1); cpc(); cpw<1>(); } else cpw<0>();
        __syncthreads();
        const float* As_=sm+(c&1)*9216; const float* Bs_=As_+4608;
#pragma unroll
        for(int kb=0;kb<8;kb++){
            float a[2][4];
#pragma unroll
            for(int mt=0;mt<2;mt++){
                int r=wm*32+mt*16+g;
                a[mt][0]=As_[r*72+kb*8+tg];     a[mt][1]=As_[(r+8)*72+kb*8+tg];
                a[mt][2]=As_[r*72+kb*8+tg+4];   a[mt][3]=As_[(r+8)*72+kb*8+tg+4];
            }
#pragma unroll
            for(int nt=0;nt<4;nt++){
                int cc=wn*32+nt*8+g;
                float b0=Bs_[(kb*8+tg)*72+cc], b1=Bs_[(kb*8+tg+4)*72+cc];
                mma8(acc[0][nt],a[0][0],a[0][1],a[0][2],a[0][3],b0,b1);
                mma8(acc[1][nt],a[1][0],a[1][1],a[1][2],a[1][3],b0,b1);
            }
        }
        __syncthreads();
    }
#pragma unroll
    for(int nt=0;nt<4;nt++){
        int cc=col0+wn*32+nt*8+tg*2;
        float bx=bias[cc], by=bias[cc+1];
#pragma unroll
        for(int mt=0;mt<2;mt++){
            int r=row0+wm*32+mt*16+g;
            float2 v0={acc[mt][nt][0]+bx, acc[mt][nt][1]+by};
            float2 v1={acc[mt][nt][2]+bx, acc[mt][nt][3]+by};
            *(float2*)&C[(size_t)r*G4+cc]=v0;
            *(float2*)&C[(size_t)(r+8)*G4+cc]=v1;
        }
    }
}

// ---------------- persistent LSTM layer ----------------
// 128 CTAs = 4 bg x 32 strips; 512 threads = 4 warp-groups, 4-way K-split.
// One barrier per chunk (issue-ahead-2 AFTER barrier is stage-safe).
// Distributed all-to-all epoch flags for the per-bg grid barrier.
__global__ __launch_bounds__(512) void lstm_k(const float* __restrict__ xz,
        float* __restrict__ hout, const float* __restrict__ Wr, unsigned base){
    extern __shared__ float sm[];
    float2* Wpk=(float2*)sm;            // 16384 float2 = 128 KB
    const int tid=threadIdx.x, l=tid&31, w=tid>>5;
    const int wg=w>>2, wl=w&3;
    const int wm=wl>>1, wn=wl&1;
    const int g=l>>2, tg=l&3;
    const int wtid=tid&127;
    const int strip=blockIdx.x&31, bg=blockIdx.x>>5;
    float* As0=sm+32768+wg*4096;        // 4 stages x 1024 floats per wg
    const int barid=wg+1;

    // prepack Wr slice into B-fragment lane order
    for(int e=tid;e<16384;e+=512){
        int tg_=e&3, ci=(e>>2)&63, kb=e>>8;
        int nt=ci>>4, wn_=(ci>>3)&1, gg=ci&7;
        int gcol=nt*HID + strip*16 + wn_*8 + gg;
        int k0=kb*8+tg_;
        float2 v; v.x=rna(Wr[(size_t)k0*G4+gcol]); v.y=rna(Wr[(size_t)(k0+4)*G4+gcol]);
        Wpk[e]=v;
    }
    __syncthreads();

    float cst[2][4];
#pragma unroll
    for(int m=0;m<2;m++) for(int q=0;q<4;q++) cst[m][q]=0.f;
    float xzp[2][4][4];

    auto pfxz=[&](int tt){
        const float* xr=xz+(size_t)tt*BAT*G4;
#pragma unroll
        for(int mt=0;mt<2;mt++)
#pragma unroll
            for(int nt=0;nt<4;nt++){
                int b=bg*64+wm*32+mt*16+g;
                int cc=nt*HID+strip*16+wn*8+tg*2;
                float2 v0=*(const float2*)&xr[(size_t)b*G4+cc];
                float2 v1=*(const float2*)&xr[(size_t)(b+8)*G4+cc];
                xzp[mt][nt][0]=v0.x; xzp[mt][nt][1]=v0.y;
                xzp[mt][nt][2]=v1.x; xzp[mt][nt][3]=v1.y;
            }
    };
    if(wg==1) pfxz(0);

    for(int t=0;t<TST;t++){
        // ---- wait for all 32 CTAs of this bg to have finished step t-1 ----
        if(t>0){
            if(tid<32){
                const volatile unsigned* f=&g_sync[(bg*32+tid)*32];
                unsigned tgt=base+(unsigned)t;
                while(*f < tgt){}
            }
            __threadfence();
            __syncthreads();
        }

        const float* hb=g_Hb[t&1];
        float* hn=g_Hb[(t&1)^1];

        auto issueA=[&](int c){
            float* dst=As0+(c&3)*1024;
            const int kb0=wg*16+c*2;
#pragma unroll
            for(int q=0;q<2;q++){
                int r=wtid>>1, hf=wtid&1;
                cp16(su32(dst+(q*64+r)*8+hf*4),
                     hb + ((size_t)(kb0+q)*BAT + bg*64 + r)*8 + hf*4);
            }
        };
        issueA(0); cpc();
        issueA(1); cpc();

        float acc[2][4][4];
        if(wg==1){
#pragma unroll
            for(int mt=0;mt<2;mt++) for(int nt=0;nt<4;nt++) for(int q=0;q<4;q++)
                acc[mt][nt][q]=xzp[mt][nt][q];
            if(t+1<TST) pfxz(t+1);
        } else {
#pragma unroll
            for(int m=0;m<2;m++) for(int n=0;n<4;n++) for(int q=0;q<4;q++)
                acc[m][n][q]=0.f;
        }

        for(int c=0;c<8;c++){
            if(c<7) cpw<1>(); else cpw<0>();
            barwg(barid);
            if(c<6){ issueA(c+2); cpc(); }
            const float* A_=As0+(c&3)*1024;
#pragma unroll
            for(int kbl=0;kbl<2;kbl++){
                const int kbg=wg*16+c*2+kbl;
                float2 v0[2], v1[2];
#pragma unroll
                for(int mt=0;mt<2;mt++){
                    int r=wm*32+mt*16+g;
                    v0[mt]=*(const float2*)&A_[(kbl*64+r)*8+tg*2];
                    v1[mt]=*(const float2*)&A_[(kbl*64+r+8)*8+tg*2];
                }
#pragma unroll
                for(int nt=0;nt<4;nt++){
                    float2 bv=Wpk[(kbg*64 + nt*16+wn*8+g)*4 + tg];
                    mma8(acc[0][nt], v0[0].x,v1[0].x,v0[0].y,v1[0].y, bv.x,bv.y);
                    mma8(acc[1][nt], v0[1].x,v1[1].x,v0[1].y,v1[1].y, bv.x,bv.y);
                }
            }
        }
        barwg(barid);   // all same-wg warps done with As before red overwrite

        // K-split reduction: wg1..3 dump acc (float4, rotated swizzle) into own As region
        if(wg!=0){
            float4* redw=(float4*)As0;
#pragma unroll
            for(int mt=0;mt<2;mt++)
#pragma unroll
                for(int nt=0;nt<4;nt++){
                    int jj=mt*4+nt;
                    float4 v={acc[mt][nt][0],acc[mt][nt][1],acc[mt][nt][2],acc[mt][nt][3]};
                    redw[wtid*8 + ((jj+wtid)&7)]=v;
                }
        }
        __syncthreads();
        if(wg==0){
#pragma unroll
            for(int mt=0;mt<2;mt++){
                float hq[2][2];
#pragma unroll
                for(int nt=0;nt<4;nt++){
                    int jj=mt*4+nt;
#pragma unroll
                    for(int ww=1;ww<4;ww++){
                        const float4* redw=(const float4*)(sm+32768+ww*4096);
                        float4 v=redw[wtid*8 + ((jj+wtid)&7)];
                        acc[mt][nt][0]+=v.x; acc[mt][nt][1]+=v.y;
                        acc[mt][nt][2]+=v.z; acc[mt][nt][3]+=v.w;
                    }
                }
#pragma unroll
                for(int q=0;q<4;q++){
                    float ig=sigf(acc[mt][0][q]);
                    float fg=sigf(acc[mt][1][q]);
                    float gv=tanhf_(acc[mt][2][q]);
                    float og=sigf(acc[mt][3][q]);
                    float cc_=fg*cst[mt][q]+ig*gv;
                    cst[mt][q]=cc_;
                    hq[q>>1][q&1]=rna(og*tanhf_(cc_));
                }
#pragma unroll
                for(int p=0;p<2;p++){
                    int b=bg*64+wm*32+mt*16+p*8+g;
                    int U0=strip*16+wn*8+tg*2;
                    float2 hv={hq[p][0],hq[p][1]};
                    *(float2*)&hout[(size_t)(t*BAT+b)*HID+U0]=hv;
#pragma unroll
                    for(int s=0;s<2;s++){
                        int U=U0+s;
                        int kb=U>>3, kp=U&7, j=(kp&3)*2+(kp>>2);
                        hn[((size_t)kb*BAT+b)*8+j]=hq[p][s];
                    }
                }
            }
            barwg(1);                      // wg0 stores complete
            if(tid==0){
                __threadfence();
                g_sync[(bg*32+strip)*32]=base+(unsigned)(t+1);
            }
        }
    }
}

// ---------------- heads ----------------
__global__ __launch_bounds__(256) void head_k(const float* __restrict__ h,
        const float* __restrict__ Wmu, const float* __restrict__ bmu,
        const float* __restrict__ Wsig, const float* __restrict__ bsig,
        float* __restrict__ out){
    int w=threadIdx.x>>5, l=threadIdx.x&31;
    int r=blockIdx.x*8+w;
    const float* hr=h+(size_t)r*HID;
    float smu=0.f, ssg=0.f;
    for(int k=l;k<HID;k+=32){ float hv=hr[k]; smu+=hv*Wmu[k]; ssg+=hv*Wsig[k]; }
#pragma unroll
    for(int o=16;o;o>>=1){
        smu+=__shfl_xor_sync(0xFFFFFFFFu,smu,o);
        ssg+=__shfl_xor_sync(0xFFFFFFFFu,ssg,o);
    }
    if(l==0){
        int t=r>>8, b=r&255;
        out[b*TST+t]=smu+bmu[0];
        float x=ssg+bsig[0];
        out[RWS + b*TST+t]=(x>20.f)? x : log1pf(__expf(x));
    }
}

extern "C" void kernel_launch(void* const* d_in, const int* in_sizes, int n_in,
                              void* d_out, int out_size){
    const float* xc  =(const float*)d_in[0];
    const int*   c0  =(const int*  )d_in[1];
    const int*   c1  =(const int*  )d_in[2];
    const float* e0  =(const float*)d_in[3];
    const float* e1  =(const float*)d_in[4];
    const float* Wk1 =(const float*)d_in[5];
    const float* Wr1 =(const float*)d_in[6];
    const float* b1  =(const float*)d_in[7];
    const float* Wk2 =(const float*)d_in[8];
    const float* Wr2 =(const float*)d_in[9];
    const float* b2  =(const float*)d_in[10];
    const float* Wmu =(const float*)d_in[11];
    const float* bmu =(const float*)d_in[12];
    const float* Wsig=(const float*)d_in[13];
    const float* bsig=(const float*)d_in[14];
    float* out=(float*)d_out;

    cudaFuncSetAttribute(lstm_k, cudaFuncAttributeMaxDynamicSharedMemorySize, 196608);
    cudaFuncSetAttribute(gemm64, cudaFuncAttributeMaxDynamicSharedMemorySize, 73728);

    void *pX,*pXZ,*pH1,*pH2,*pW1,*pW2;
    cudaGetSymbolAddress(&pX,  g_X);
    cudaGetSymbolAddress(&pXZ, g_XZ);
    cudaGetSymbolAddress(&pH1, g_H1);
    cudaGetSymbolAddress(&pH2, g_H2);
    cudaGetSymbolAddress(&pW1, g_Wk1p);
    cudaGetSymbolAddress(&pW2, g_Wk2r);

    prep_k<<<4096,256>>>(xc,c0,c1,e0,e1,Wk1,Wk2);
    zero_k<<<1024,256>>>();
    gemm64<<<dim3(32,RWS/64),128,73728>>>((const float*)pX,(const float*)pW1,b1,(float*)pXZ,64);
    lstm_k<<<128,512,196608>>>((const float*)pXZ,(float*)pH1,Wr1,0u);
    zero_k<<<1024,256>>>();
    gemm64<<<dim3(32,RWS/64),128,73728>>>((const float*)pH1,(const float*)pW2,b2,(float*)pXZ,512);
    lstm_k<<<128,512,196608>>>((const float*)pXZ,(float*)pH2,Wr2,192u);
    head_k<<<RWS/8,256>>>((const float*)pH2,Wmu,bmu,Wsig,bsig,out);
    rst_k<<<1,128>>>();
}

// round 7
// speedup vs baseline: 1.4845x; 1.3969x over previous
#include <cuda_runtime.h>
#include <cuda_bf16.h>
#include <cstdint>
#include <cstddef>

#define TST 192
#define BAT 256
#define HID 512
#define G4  2048
#define RWS (TST*BAT)

__device__ __nv_bfloat16 g_X[(size_t)RWS*64];
__device__ float g_XZ[(size_t)RWS*G4];
__device__ __nv_bfloat16 g_H1[(size_t)RWS*HID];
__device__ __nv_bfloat16 g_H2[(size_t)RWS*HID];
__device__ unsigned g_Hb[2][32*BAT*8];   // packed bf16 h ping-pong [kb16][b][tg]uint2
__device__ unsigned g_Wk1p[32*G4];       // packed bf16 pairs along k (k padded to 64)
__device__ unsigned g_Wk2r[256*G4];
__device__ volatile unsigned g_sync[4096];   // 128 flags, one per 128B line

__device__ __forceinline__ unsigned pk2(float x, float y){
    __nv_bfloat162 t=__floats2bfloat162_rn(x,y);
    return *(unsigned*)&t;
}
__device__ __forceinline__ void mma16(float* d, unsigned a0,unsigned a1,unsigned a2,
                                      unsigned a3, unsigned b0,unsigned b1){
    asm volatile("mma.sync.aligned.m16n8k16.row.col.f32.bf16.bf16.f32 "
        "{%0,%1,%2,%3}, {%4,%5,%6,%7}, {%8,%9}, {%0,%1,%2,%3};\n"
        : "+f"(d[0]),"+f"(d[1]),"+f"(d[2]),"+f"(d[3])
        : "r"(a0),"r"(a1),"r"(a2),"r"(a3),"r"(b0),"r"(b1));
}
__device__ __forceinline__ unsigned su32(const void* p){
    return (unsigned)__cvta_generic_to_shared(p);
}
__device__ __forceinline__ void cp16(unsigned dst, const void* src){
    asm volatile("cp.async.cg.shared.global [%0], [%1], 16;" :: "r"(dst), "l"(src));
}
__device__ __forceinline__ void cpc(){ asm volatile("cp.async.commit_group;"); }
template<int N> __device__ __forceinline__ void cpw(){
    asm volatile("cp.async.wait_group %0;" :: "n"(N));
}
__device__ __forceinline__ void barwg(int id){
    asm volatile("bar.sync %0, 128;" :: "r"(id) : "memory");
}
__device__ __forceinline__ float sigf(float x){ return 1.f/(1.f+__expf(-x)); }
__device__ __forceinline__ float tanhf_(float x){
    float e=__expf(-2.f*fabsf(x)); return copysignf((1.f-e)/(1.f+e), x);
}

// ---------------- prep: embed/concat + weight packing (bf16) ----------------
__global__ void prep_k(const float* __restrict__ xc, const int* __restrict__ c0,
                       const int* __restrict__ c1, const float* __restrict__ e0,
                       const float* __restrict__ e1, const float* __restrict__ Wk1,
                       const float* __restrict__ Wk2){
    const size_t N1=(size_t)RWS*64, N2=N1+32*G4, NT=N2+(size_t)256*G4;
    for(size_t i=(size_t)blockIdx.x*blockDim.x+threadIdx.x; i<NT;
        i+=(size_t)gridDim.x*blockDim.x){
        if(i<N1){
            int r=(int)(i>>6), cc=(int)(i&63), t=r>>8, b=r&255;
            float v=0.f;
            if(cc<8)       v=xc[(b*TST+t)*8+cc];
            else if(cc<40) v=e0[(size_t)c0[b*TST+t]*32+(cc-8)];
            else if(cc<56) v=e1[(size_t)c1[b*TST+t]*16+(cc-40)];
            g_X[i]=__float2bfloat16_rn(v);
        } else if(i<N2){
            size_t j=i-N1; int jr=(int)(j>>11), n=(int)(j&2047);
            float v0=(2*jr<56)?   Wk1[(size_t)(2*jr)*G4+n]   : 0.f;
            float v1=(2*jr+1<56)? Wk1[(size_t)(2*jr+1)*G4+n] : 0.f;
            g_Wk1p[j]=pk2(v0,v1);
        } else {
            size_t j=i-N2; int jr=(int)(j>>11), n=(int)(j&2047);
            g_Wk2r[j]=pk2(Wk2[(size_t)(2*jr)*G4+n], Wk2[(size_t)(2*jr+1)*G4+n]);
        }
    }
}

__global__ void zero_k(){
    int i=blockIdx.x*blockDim.x+threadIdx.x;
    if(i<2*32*BAT*8) ((unsigned*)g_Hb)[i]=0u;
}

__global__ void rst_k(){
    if(threadIdx.x<128) g_sync[threadIdx.x*32]=0u;
}

// ---------------- GEMM: C[M,2048] = A[M,K]@W[K,2048] + bias (bf16 in, f32 out)
// Wp: packed u32 pairs along k: Wp[j][n] = {W[2j][n], W[2j+1][n]}
__global__ __launch_bounds__(128) void gemm64(const __nv_bfloat16* __restrict__ A,
        const unsigned* __restrict__ Wp, const float* __restrict__ bias,
        float* __restrict__ C, int K){
    extern __shared__ float sm[];
    const int tid=threadIdx.x, l=tid&31, w=tid>>5, wm=w>>1, wn=w&1;
    const int g=l>>2, tg=l&3;
    const int row0=blockIdx.y*64, col0=blockIdx.x*64;
    float acc[2][4][4];
#pragma unroll
    for(int m=0;m<2;m++) for(int n=0;n<4;n++) for(int q=0;q<4;q++) acc[m][n][q]=0.f;
    const int NC=K>>6;

    auto issue=[&](int c){
        unsigned* Au=(unsigned*)(sm+(c&1)*4608);
        unsigned* Bu=Au+2304;
#pragma unroll
        for(int q=0;q<4;q++){ int e=tid+128*q, r=e>>3, s=e&7;
            cp16(su32(Au+r*36+s*4), A+(size_t)(row0+r)*K + c*64 + s*8); }
#pragma unroll
        for(int q=0;q<4;q++){ int e=tid+128*q, j=e>>4, s=e&15;
            cp16(su32(Bu+j*72+s*4), Wp+(size_t)(c*32+j)*G4 + col0 + s*4); }
    };
    issue(0); cpc();
    for(int c=0;c<NC;c++){
        if(c+1<NC){ issue(c+1); cpc(); cpw<1>(); } else cpw<0>();
        __syncthreads();
        const unsigned* Au=(const unsigned*)(sm+(c&1)*4608);
        const unsigned* Bu=Au+2304;
#pragma unroll
        for(int kb=0;kb<4;kb++){
            unsigned a[2][4];
#pragma unroll
            for(int mt=0;mt<2;mt++){
                int r=wm*32+mt*16+g;
                a[mt][0]=Au[r*36+kb*8+tg];       a[mt][1]=Au[(r+8)*36+kb*8+tg];
                a[mt][2]=Au[r*36+kb*8+tg+4];     a[mt][3]=Au[(r+8)*36+kb*8+tg+4];
            }
#pragma unroll
            for(int nt=0;nt<4;nt++){
                int cc=wn*32+nt*8+g;
                unsigned b0=Bu[(kb*8+tg)*72+cc], b1=Bu[(kb*8+tg+4)*72+cc];
                mma16(acc[0][nt],a[0][0],a[0][1],a[0][2],a[0][3],b0,b1);
                mma16(acc[1][nt],a[1][0],a[1][1],a[1][2],a[1][3],b0,b1);
            }
        }
        __syncthreads();
    }
#pragma unroll
    for(int nt=0;nt<4;nt++){
        int cc=col0+wn*32+nt*8+tg*2;
        float bx=bias[cc], by=bias[cc+1];
#pragma unroll
        for(int mt=0;mt<2;mt++){
            int r=row0+wm*32+mt*16+g;
            float2 v0={acc[mt][nt][0]+bx, acc[mt][nt][1]+by};
            float2 v1={acc[mt][nt][2]+bx, acc[mt][nt][3]+by};
            *(float2*)&C[(size_t)r*G4+cc]=v0;
            *(float2*)&C[(size_t)(r+8)*G4+cc]=v1;
        }
    }
}

// ---------------- persistent LSTM layer (bf16 mma) ----------------
// 128 CTAs = 4 bg x 32 strips; 512 threads = 4 wg, 4-way K-split (128 k each).
// Per wg: 8 kb16 blocks, 2 chunks of 4, double-buffered. 3 wg-barriers/step.
__global__ __launch_bounds__(512) void lstm_k(const float* __restrict__ xz,
        __nv_bfloat16* __restrict__ hout, const float* __restrict__ Wr,
        unsigned base){
    extern __shared__ float sm[];
    uint2* Wpk=(uint2*)sm;              // 8192 uint2 = 64 KB
    const int tid=threadIdx.x, l=tid&31, w=tid>>5;
    const int wg=w>>2, wl=w&3;
    const int wm=wl>>1, wn=wl&1;
    const int g=l>>2, tg=l&3;
    const int wtid=tid&127;
    const int strip=blockIdx.x&31, bg=blockIdx.x>>5;
    const int barid=wg+1;

    // prepack Wr slice (bf16): Wpk[(kb*64+ci)*4+tg] =
    //   { pk(Wr[kb*16+2tg][gcol], Wr[kb*16+2tg+1][gcol]),
    //     pk(Wr[kb*16+2tg+8][gcol], Wr[kb*16+2tg+9][gcol]) }
    for(int e=tid;e<8192;e+=512){
        int tg_=e&3, ci=(e>>2)&63, kb=e>>8;
        int nt=ci>>4, wn_=(ci>>3)&1, gg=ci&7;
        int gcol=nt*HID + strip*16 + wn_*8 + gg;
        int k0=kb*16+tg_*2;
        uint2 v;
        v.x=pk2(Wr[(size_t)k0*G4+gcol],     Wr[(size_t)(k0+1)*G4+gcol]);
        v.y=pk2(Wr[(size_t)(k0+8)*G4+gcol], Wr[(size_t)(k0+9)*G4+gcol]);
        Wpk[e]=v;
    }
    __syncthreads();

    float cst[2][4];
#pragma unroll
    for(int m=0;m<2;m++) for(int q=0;q<4;q++) cst[m][q]=0.f;
    float xzp[2][4][4];

    auto pfxz=[&](int tt){
        const float* xr=xz+(size_t)tt*BAT*G4;
#pragma unroll
        for(int mt=0;mt<2;mt++)
#pragma unroll
            for(int nt=0;nt<4;nt++){
                int b=bg*64+wm*32+mt*16+g;
                int cc=nt*HID+strip*16+wn*8+tg*2;
                float2 v0=*(const float2*)&xr[(size_t)b*G4+cc];
                float2 v1=*(const float2*)&xr[(size_t)(b+8)*G4+cc];
                xzp[mt][nt][0]=v0.x; xzp[mt][nt][1]=v0.y;
                xzp[mt][nt][2]=v1.x; xzp[mt][nt][3]=v1.y;
            }
    };
    if(wg==1) pfxz(0);

    for(int t=0;t<TST;t++){
        if(t>0){
            if(tid<32){
                const volatile unsigned* f=&g_sync[(bg*32+tid)*32];
                unsigned tgt=base+(unsigned)t;
                while(*f < tgt){}
            }
            __threadfence();
            __syncthreads();
        }

        const unsigned* hb=g_Hb[t&1];
        unsigned* hn=g_Hb[(t&1)^1];

        auto issueA=[&](int c){
            float* dst=sm+16384+wg*4096+(c&1)*2048;
#pragma unroll
            for(int q=0;q<4;q++){
                int e=wtid+128*q;
                int kbl=e>>7, rem=e&127, r=rem>>1, hf=rem&1;
                int kb=wg*8+c*4+kbl;
                cp16(su32(dst+(kbl*64+r)*8+hf*4),
                     hb + ((size_t)(kb*BAT) + bg*64 + r)*8 + hf*4);
            }
        };
        issueA(0); cpc();
        issueA(1); cpc();

        float acc[2][4][4];
        if(wg==1){
#pragma unroll
            for(int mt=0;mt<2;mt++) for(int nt=0;nt<4;nt++) for(int q=0;q<4;q++)
                acc[mt][nt][q]=xzp[mt][nt][q];
            if(t+1<TST) pfxz(t+1);
        } else {
#pragma unroll
            for(int m=0;m<2;m++) for(int n=0;n<4;n++) for(int q=0;q<4;q++)
                acc[m][n][q]=0.f;
        }

#pragma unroll
        for(int c=0;c<2;c++){
            if(c==0) cpw<1>(); else cpw<0>();
            barwg(barid);
            const unsigned* Au=(const unsigned*)(sm+16384+wg*4096+(c&1)*2048);
#pragma unroll
            for(int kbl=0;kbl<4;kbl++){
                const int kbg=wg*8+c*4+kbl;
                uint2 x0[2], x1[2];
#pragma unroll
                for(int mt=0;mt<2;mt++){
                    int r=wm*32+mt*16+g;
                    x0[mt]=*(const uint2*)&Au[(kbl*64+r)*8+tg*2];
                    x1[mt]=*(const uint2*)&Au[(kbl*64+r+8)*8+tg*2];
                }
#pragma unroll
                for(int nt=0;nt<4;nt++){
                    uint2 bv=Wpk[(kbg*64 + nt*16+wn*8+g)*4 + tg];
                    mma16(acc[0][nt], x0[0].x,x1[0].x,x0[0].y,x1[0].y, bv.x,bv.y);
                    mma16(acc[1][nt], x0[1].x,x1[1].x,x0[1].y,x1[1].y, bv.x,bv.y);
                }
            }
        }
        barwg(barid);   // wg done with stages before reduction overwrite

        // K-split reduction: wg1..3 dump acc into own A region (float4, rotated)
        if(wg!=0){
            float4* redw=(float4*)(sm+16384+wg*4096);
#pragma unroll
            for(int mt=0;mt<2;mt++)
#pragma unroll
                for(int nt=0;nt<4;nt++){
                    int jj=mt*4+nt;
                    float4 v={acc[mt][nt][0],acc[mt][nt][1],acc[mt][nt][2],acc[mt][nt][3]};
                    redw[wtid*8 + ((jj+wtid)&7)]=v;
                }
        }
        __syncthreads();
        if(wg==0){
#pragma unroll
            for(int mt=0;mt<2;mt++){
                float hq[2][2];
#pragma unroll
                for(int nt=0;nt<4;nt++){
                    int jj=mt*4+nt;
#pragma unroll
                    for(int ww=1;ww<4;ww++){
                        const float4* redw=(const float4*)(sm+16384+ww*4096);
                        float4 v=redw[wtid*8 + ((jj+wtid)&7)];
                        acc[mt][nt][0]+=v.x; acc[mt][nt][1]+=v.y;
                        acc[mt][nt][2]+=v.z; acc[mt][nt][3]+=v.w;
                    }
                }
#pragma unroll
                for(int q=0;q<4;q++){
                    float ig=sigf(acc[mt][0][q]);
                    float fg=sigf(acc[mt][1][q]);
                    float gv=tanhf_(acc[mt][2][q]);
                    float og=sigf(acc[mt][3][q]);
                    float cc_=fg*cst[mt][q]+ig*gv;
                    cst[mt][q]=cc_;
                    hq[q>>1][q&1]=og*tanhf_(cc_);
                }
#pragma unroll
                for(int p=0;p<2;p++){
                    int b=bg*64+wm*32+mt*16+p*8+g;
                    int U0=strip*16+wn*8+tg*2;
                    unsigned pv=pk2(hq[p][0],hq[p][1]);
                    *(unsigned*)&hout[(size_t)(t*BAT+b)*HID+U0]=pv;
                    hn[((size_t)(strip*BAT)+b)*8 + tg*2 + wn]=pv;
                }
            }
            barwg(1);
            if(tid==0){
                __threadfence();
                g_sync[(bg*32+strip)*32]=base+(unsigned)(t+1);
            }
        }
    }
}

// ---------------- heads ----------------
__global__ __launch_bounds__(256) void head_k(const __nv_bfloat16* __restrict__ h,
        const float* __restrict__ Wmu, const float* __restrict__ bmu,
        const float* __restrict__ Wsig, const float* __restrict__ bsig,
        float* __restrict__ out){
    int w=threadIdx.x>>5, l=threadIdx.x&31;
    int r=blockIdx.x*8+w;
    const __nv_bfloat16* hr=h+(size_t)r*HID;
    float smu=0.f, ssg=0.f;
    for(int k=l;k<HID;k+=32){
        float hv=__bfloat162float(hr[k]);
        smu+=hv*Wmu[k]; ssg+=hv*Wsig[k];
    }
#pragma unroll
    for(int o=16;o;o>>=1){
        smu+=__shfl_xor_sync(0xFFFFFFFFu,smu,o);
        ssg+=__shfl_xor_sync(0xFFFFFFFFu,ssg,o);
    }
    if(l==0){
        int t=r>>8, b=r&255;
        out[b*TST+t]=smu+bmu[0];
        float x=ssg+bsig[0];
        out[RWS + b*TST+t]=(x>20.f)? x : log1pf(__expf(x));
    }
}

extern "C" void kernel_launch(void* const* d_in, const int* in_sizes, int n_in,
                              void* d_out, int out_size){
    const float* xc  =(const float*)d_in[0];
    const int*   c0  =(const int*  )d_in[1];
    const int*   c1  =(const int*  )d_in[2];
    const float* e0  =(const float*)d_in[3];
    const float* e1  =(const float*)d_in[4];
    const float* Wk1 =(const float*)d_in[5];
    const float* Wr1 =(const float*)d_in[6];
    const float* b1  =(const float*)d_in[7];
    const float* Wk2 =(const float*)d_in[8];
    const float* Wr2 =(const float*)d_in[9];
    const float* b2  =(const float*)d_in[10];
    const float* Wmu =(const float*)d_in[11];
    const float* bmu =(const float*)d_in[12];
    const float* Wsig=(const float*)d_in[13];
    const float* bsig=(const float*)d_in[14];
    float* out=(float*)d_out;

    cudaFuncSetAttribute(lstm_k, cudaFuncAttributeMaxDynamicSharedMemorySize, 131072);
    cudaFuncSetAttribute(gemm64, cudaFuncAttributeMaxDynamicSharedMemorySize, 36864);

    void *pX,*pXZ,*pH1,*pH2,*pW1,*pW2;
    cudaGetSymbolAddress(&pX,  g_X);
    cudaGetSymbolAddress(&pXZ, g_XZ);
    cudaGetSymbolAddress(&pH1, g_H1);
    cudaGetSymbolAddress(&pH2, g_H2);
    cudaGetSymbolAddress(&pW1, g_Wk1p);
    cudaGetSymbolAddress(&pW2, g_Wk2r);

    prep_k<<<4096,256>>>(xc,c0,c1,e0,e1,Wk1,Wk2);
    zero_k<<<512,256>>>();
    gemm64<<<dim3(32,RWS/64),128,36864>>>((const __nv_bfloat16*)pX,
        (const unsigned*)pW1,b1,(float*)pXZ,64);
    lstm_k<<<128,512,131072>>>((const float*)pXZ,(__nv_bfloat16*)pH1,Wr1,0u);
    zero_k<<<512,256>>>();
    gemm64<<<dim3(32,RWS/64),128,36864>>>((const __nv_bfloat16*)pH1,
        (const unsigned*)pW2,b2,(float*)pXZ,512);
    lstm_k<<<128,512,131072>>>((const float*)pXZ,(__nv_bfloat16*)pH2,Wr2,192u);
    head_k<<<RWS/8,256>>>((const __nv_bfloat16*)pH2,Wmu,bmu,Wsig,bsig,out);
    rst_k<<<1,128>>>();
}